// round 3
// baseline (speedup 1.0000x reference)
#include <cuda_runtime.h>
#include <cuda_bf16.h>
#include <cstdint>

#define Nn   2048
#define IND  128
#define HIDD 64
#define Ee   32768
#define EPSf 1e-5f
#define NOUT 4096   /* HIDD*HIDD */
#define KK   256    /* split K = 2*IND */

// -------- scratch (device globals; no allocation allowed) --------
__device__ __align__(256) float g_p1[Nn * NOUT];        // relu(h@W1+b1)
__device__ __align__(256) float g_p2[Nn * HIDD];        // relu(h@Wp2+bp2)
__device__ __align__(256) unsigned short g_h2[Nn * KK];     // [row][k']: k'<128 hi, >=128 lo
__device__ __align__(256) unsigned short g_w12t[NOUT * KK]; // [n][k'] transposed split W1
__device__ int g_cnt[Nn];
__device__ int g_off[Nn + 1];
__device__ int g_cur[Nn];
__device__ int g_eidx[Ee];

// ================= edge bucketing by src =================
__global__ void k_zero() {
    int i = blockIdx.x * blockDim.x + threadIdx.x;
    if (i < Nn) g_cnt[i] = 0;
}
__global__ void k_hist(const int* __restrict__ src) {
    int e = blockIdx.x * blockDim.x + threadIdx.x;
    if (e < Ee) atomicAdd(&g_cnt[src[e]], 1);
}
__global__ void k_scan() {
    __shared__ int part[256];
    int t = threadIdx.x;
    int base = t * 8;
    int loc[8];
    int s = 0;
#pragma unroll
    for (int i = 0; i < 8; i++) { loc[i] = g_cnt[base + i]; s += loc[i]; }
    part[t] = s;
    __syncthreads();
    if (t == 0) {
        int run = 0;
        for (int i = 0; i < 256; i++) { int v = part[i]; part[i] = run; run += v; }
    }
    __syncthreads();
    int run = part[t];
#pragma unroll
    for (int i = 0; i < 8; i++) {
        g_off[base + i] = run;
        g_cur[base + i] = run;
        run += loc[i];
    }
    if (t == 255) g_off[Nn] = run;
}
__global__ void k_scatter(const int* __restrict__ src) {
    int e = blockIdx.x * blockDim.x + threadIdx.x;
    if (e < Ee) {
        int s = src[e];
        int p = atomicAdd(&g_cur[s], 1);
        g_eidx[p] = e;
    }
}

// ================= bf16 split conversion =================
__device__ __forceinline__ void split_bf16(float x, unsigned short& hs, unsigned short& ls) {
    __nv_bfloat16 bh = __float2bfloat16(x);
    float r = x - __bfloat162float(bh);
    __nv_bfloat16 bl = __float2bfloat16(r);
    hs = __bfloat16_as_ushort(bh);
    ls = __bfloat16_as_ushort(bl);
}

__global__ void k_cvt_h(const float* __restrict__ h) {
    int idx = blockIdx.x * blockDim.x + threadIdx.x;   // over Nn*IND
    if (idx >= Nn * IND) return;
    int row = idx >> 7, c = idx & 127;
    unsigned short hs, ls;
    split_bf16(h[idx], hs, ls);
    g_h2[row * KK + c] = hs;
    g_h2[row * KK + 128 + c] = ls;
}

__global__ void k_cvt_w(const float* __restrict__ W1) {
    int idx = blockIdx.x * blockDim.x + threadIdx.x;   // over IND*NOUT
    if (idx >= IND * NOUT) return;
    int k = idx >> 12, n = idx & 4095;                 // read coalesced along n
    unsigned short hs, ls;
    split_bf16(W1[idx], hs, ls);
    g_w12t[n * KK + k] = hs;
    g_w12t[n * KK + 128 + k] = ls;
}

// ================= p1 = relu(h @ W1 + b1) via mma.sync bf16 (split) =================
// Block: 128(M) x 128(N), 8 warps (2x4), warp tile 64x32, K chunked by 64.
#define KC     64
#define SSTR   72   /* padded k-stride in bf16: 144B = 16 mod 128 -> conflict-free */

__global__ __launch_bounds__(256) void k_p1mma(const float* __restrict__ b1) {
    __shared__ __align__(16) unsigned short As[128 * SSTR];
    __shared__ __align__(16) unsigned short Bs[128 * SSTR];

    int tid = threadIdx.x;
    int wid = tid >> 5, lane = tid & 31;
    int g = lane >> 2, t = lane & 3;
    int warp_m = (wid >> 2) * 64;     // 0 or 64
    int warp_n = (wid & 3) * 32;      // 0,32,64,96
    int row0 = blockIdx.y * 128;
    int col0 = blockIdx.x * 128;

    float acc[4][4][4];
#pragma unroll
    for (int mi = 0; mi < 4; mi++)
#pragma unroll
        for (int ni = 0; ni < 4; ni++)
#pragma unroll
            for (int r = 0; r < 4; r++) acc[mi][ni][r] = 0.f;

    for (int kc = 0; kc < KK; kc += KC) {
        // load A chunk: h2[row0+m][kc + 0..63]  (uint4 = 8 bf16)
#pragma unroll
        for (int it = 0; it < 4; it++) {
            int chunk = tid + it * 256;            // 0..1023
            int m = chunk >> 3;
            int k8 = (chunk & 7) * 8;
            uint4 v = *(const uint4*)&g_h2[(row0 + m) * KK + kc + k8];
            *(uint4*)&As[m * SSTR + k8] = v;
        }
        // load B chunk: w12t[col0+n][kc + 0..63]
#pragma unroll
        for (int it = 0; it < 4; it++) {
            int chunk = tid + it * 256;
            int n = chunk >> 3;
            int k8 = (chunk & 7) * 8;
            uint4 v = *(const uint4*)&g_w12t[(col0 + n) * KK + kc + k8];
            *(uint4*)&Bs[n * SSTR + k8] = v;
        }
        __syncthreads();

#pragma unroll
        for (int ks = 0; ks < KC; ks += 16) {
            uint32_t a[4][4], b[4][2];
#pragma unroll
            for (int mi = 0; mi < 4; mi++) {
                int r = warp_m + mi * 16 + g;
                const unsigned short* p0 = &As[r * SSTR + ks + t * 2];
                const unsigned short* p1 = &As[(r + 8) * SSTR + ks + t * 2];
                a[mi][0] = *(const uint32_t*)(p0);
                a[mi][1] = *(const uint32_t*)(p1);
                a[mi][2] = *(const uint32_t*)(p0 + 8);
                a[mi][3] = *(const uint32_t*)(p1 + 8);
            }
#pragma unroll
            for (int ni = 0; ni < 4; ni++) {
                int c = warp_n + ni * 8 + g;
                const unsigned short* p = &Bs[c * SSTR + ks + t * 2];
                b[ni][0] = *(const uint32_t*)(p);
                b[ni][1] = *(const uint32_t*)(p + 8);
            }
#pragma unroll
            for (int mi = 0; mi < 4; mi++)
#pragma unroll
                for (int ni = 0; ni < 4; ni++) {
                    asm volatile(
                        "mma.sync.aligned.m16n8k16.row.col.f32.bf16.bf16.f32 "
                        "{%0,%1,%2,%3}, {%4,%5,%6,%7}, {%8,%9}, {%0,%1,%2,%3};"
                        : "+f"(acc[mi][ni][0]), "+f"(acc[mi][ni][1]),
                          "+f"(acc[mi][ni][2]), "+f"(acc[mi][ni][3])
                        : "r"(a[mi][0]), "r"(a[mi][1]), "r"(a[mi][2]), "r"(a[mi][3]),
                          "r"(b[ni][0]), "r"(b[ni][1]));
                }
        }
        __syncthreads();
    }

    // epilogue: bias + relu -> g_p1
#pragma unroll
    for (int mi = 0; mi < 4; mi++) {
        int r = row0 + warp_m + mi * 16 + g;
#pragma unroll
        for (int ni = 0; ni < 4; ni++) {
            int c = col0 + warp_n + ni * 8 + t * 2;
            float2 bb = *(const float2*)&b1[c];
            float2 o0, o1;
            o0.x = fmaxf(acc[mi][ni][0] + bb.x, 0.f);
            o0.y = fmaxf(acc[mi][ni][1] + bb.y, 0.f);
            o1.x = fmaxf(acc[mi][ni][2] + bb.x, 0.f);
            o1.y = fmaxf(acc[mi][ni][3] + bb.y, 0.f);
            *(float2*)&g_p1[(size_t)r * NOUT + c] = o0;
            *(float2*)&g_p1[(size_t)(r + 8) * NOUT + c] = o1;
        }
    }
}

// ================= p2 = relu(h @ Wp2 + bp2) =================
__global__ void k_p2(const float* __restrict__ h,
                     const float* __restrict__ Wp2,
                     const float* __restrict__ bp2) {
    __shared__ float hs[IND];
    int row = blockIdx.x;
    int j = threadIdx.x;
    hs[j] = h[row * IND + j];
    hs[j + 64] = h[row * IND + j + 64];
    __syncthreads();
    float acc = bp2[j];
#pragma unroll 8
    for (int k = 0; k < IND; k++) acc += hs[k] * Wp2[k * HIDD + j];
    g_p2[row * HIDD + j] = fmaxf(acc, 0.f);
}

// ================= local branch =================
__global__ __launch_bounds__(128) void k_local(const float* __restrict__ local,
                                               const float* __restrict__ ein,
                                               const int* __restrict__ src,
                                               const int* __restrict__ dst,
                                               const float* __restrict__ ln_w,
                                               const float* __restrict__ ln_b,
                                               const float* __restrict__ conv_w,
                                               const float* __restrict__ conv_b,
                                               const float* __restrict__ W2,
                                               const float* __restrict__ b2,
                                               const float* __restrict__ bnL_g,
                                               const float* __restrict__ bnL_b,
                                               float* __restrict__ out) {
    __shared__ float W2s[IND * HIDD];
    __shared__ float Tsm[8][IND];
    __shared__ float sa[IND + 2], sb[IND + 2];
    __shared__ float4 red[4];

    int t = threadIdx.x;
    for (int i = t; i < IND * HIDD; i += 128) W2s[i] = W2[i];
    float lw = ln_w[t], lb = ln_b[t];
    float cw0 = conv_w[0], cw1 = conv_w[1], cw2 = conv_w[2];
    float cw3 = conv_w[3], cw4 = conv_w[4], cw5 = conv_w[5];
    float cb = conv_b[0];
    int e0 = blockIdx.x * 8;
    int lane = t & 31, warp = t >> 5;
    if (t == 0) { sa[0] = 0.f; sa[IND + 1] = 0.f; sb[0] = 0.f; sb[IND + 1] = 0.f; }

    for (int eo = 0; eo < 8; eo++) {
        int e = e0 + eo;
        int s = src[e], dd = dst[e];
        float a = local[s * IND + t];
        float b = local[dd * IND + t];
        float4 v = make_float4(a, a * a, b, b * b);
#pragma unroll
        for (int o = 16; o; o >>= 1) {
            v.x += __shfl_down_sync(0xffffffffu, v.x, o);
            v.y += __shfl_down_sync(0xffffffffu, v.y, o);
            v.z += __shfl_down_sync(0xffffffffu, v.z, o);
            v.w += __shfl_down_sync(0xffffffffu, v.w, o);
        }
        if (lane == 0) red[warp] = v;
        __syncthreads();
        float4 tot = red[0];
        tot.x += red[1].x + red[2].x + red[3].x;
        tot.y += red[1].y + red[2].y + red[3].y;
        tot.z += red[1].z + red[2].z + red[3].z;
        tot.w += red[1].w + red[2].w + red[3].w;
        float mua = tot.x * (1.f / IND), vara = tot.y * (1.f / IND) - mua * mua;
        float mub = tot.z * (1.f / IND), varb = tot.w * (1.f / IND) - mub * mub;
        float an = (a - mua) * rsqrtf(vara + EPSf) * lw + lb;
        float bn_ = (b - mub) * rsqrtf(varb + EPSf) * lw + lb;
        sa[t + 1] = an;
        sb[t + 1] = bn_;
        __syncthreads();
        float c = cw0 * sa[t] + cw1 * sa[t + 1] + cw2 * sa[t + 2]
                + cw3 * sb[t] + cw4 * sb[t + 1] + cw5 * sb[t + 2] + cb;
        Tsm[eo][t] = fmaxf(c, 0.f);
        __syncthreads();
    }

    int j = t & 63, half = t >> 6;
    float c0 = 0.f, c1 = 0.f, c2 = 0.f, c3 = 0.f;
#pragma unroll 4
    for (int i = 0; i < IND; i++) {
        float w = W2s[i * HIDD + j];
        c0 += Tsm[half + 0][i] * w;
        c1 += Tsm[half + 2][i] * w;
        c2 += Tsm[half + 4][i] * w;
        c3 += Tsm[half + 6][i] * w;
    }
    float rs = rsqrtf(1.f + EPSf);
    float sL = bnL_g[j] * rs, bL = bnL_b[j];
    float bb = b2[j];
    float r0 = fmaxf((c0 + bb) * sL + bL, 0.f);
    float r1 = fmaxf((c1 + bb) * sL + bL, 0.f);
    float r2 = fmaxf((c2 + bb) * sL + bL, 0.f);
    float r3 = fmaxf((c3 + bb) * sL + bL, 0.f);
    out[(e0 + half + 0) * HIDD + j] = r0 + ein[(e0 + half + 0) * HIDD + j];
    out[(e0 + half + 2) * HIDD + j] = r1 + ein[(e0 + half + 2) * HIDD + j];
    out[(e0 + half + 4) * HIDD + j] = r2 + ein[(e0 + half + 4) * HIDD + j];
    out[(e0 + half + 6) * HIDD + j] = r3 + ein[(e0 + half + 6) * HIDD + j];
}

// ================= global branch: one block per src node =================
__global__ __launch_bounds__(256) void k_global(const int* __restrict__ dst,
                                                const float* __restrict__ W3,
                                                const float* __restrict__ b3,
                                                const float* __restrict__ bng_g,
                                                const float* __restrict__ bng_b,
                                                const float* __restrict__ bnG_g,
                                                const float* __restrict__ bnG_b,
                                                float* __restrict__ out) {
    __shared__ float p1s[HIDD][HIDD + 1];   // [k][d], padded
    __shared__ float W3s[HIDD * HIDD];
    __shared__ float p2s[4][HIDD];
    __shared__ float zs[4][HIDD];

    int node = blockIdx.x;
    int t = threadIdx.x;
    int beg = g_off[node], end = g_off[node + 1];
    if (beg == end) return;

    const float* p1row = &g_p1[node * NOUT];
    for (int jdx = t; jdx < HIDD * HIDD; jdx += 256) {
        int d = jdx >> 6, k = jdx & 63;
        p1s[k][d] = p1row[jdx];
    }
    for (int jdx = t; jdx < HIDD * HIDD; jdx += 256) W3s[jdx] = W3[jdx];

    int d = t & 63, g = t >> 6;
    float rs = rsqrtf(1.f + EPSf);
    float s1 = bng_g[d] * rs, o1 = bng_b[d];
    float s2 = bnG_g[d] * rs, o2 = bnG_b[d];
    float b3v = b3[d];
    __syncthreads();

    for (int base = beg; base < end; base += 4) {
        int ei = base + g;
        bool valid = ei < end;
        int e = 0;
        if (valid) {
            e = g_eidx[ei];
            int dn = dst[e];
            p2s[g][d] = g_p2[dn * HIDD + d];
        }
        __syncthreads();
        if (valid) {
            float y = 0.f;
#pragma unroll 8
            for (int k = 0; k < HIDD; k++) y += p1s[k][d] * p2s[g][k];
            zs[g][d] = y * s1 + o1;
        }
        __syncthreads();
        if (valid) {
            float o = b3v;
#pragma unroll 8
            for (int k = 0; k < HIDD; k++) o += zs[g][k] * W3s[k * HIDD + d];
            float v = fmaxf(o * s2 + o2, 0.f);
            out[e * HIDD + d] += v;
        }
        __syncthreads();
    }
}

// ================= launch =================
extern "C" void kernel_launch(void* const* d_in, const int* in_sizes, int n_in,
                              void* d_out, int out_size) {
    const float* h      = (const float*)d_in[0];
    const float* local_ = (const float*)d_in[1];
    const float* ein    = (const float*)d_in[2];
    const int*   src    = (const int*)d_in[3];
    const int*   dst    = (const int*)d_in[4];
    const float* ln_w   = (const float*)d_in[5];
    const float* ln_b   = (const float*)d_in[6];
    const float* conv_w = (const float*)d_in[7];
    const float* conv_b = (const float*)d_in[8];
    const float* W1     = (const float*)d_in[9];
    const float* b1     = (const float*)d_in[10];
    const float* Wp2    = (const float*)d_in[11];
    const float* bp2    = (const float*)d_in[12];
    const float* W2     = (const float*)d_in[13];
    const float* b2     = (const float*)d_in[14];
    const float* W3     = (const float*)d_in[15];
    const float* b3     = (const float*)d_in[16];
    const float* bng_g  = (const float*)d_in[17];
    const float* bng_b  = (const float*)d_in[18];
    const float* bnG_g  = (const float*)d_in[19];
    const float* bnG_b  = (const float*)d_in[20];
    const float* bnL_g  = (const float*)d_in[21];
    const float* bnL_b  = (const float*)d_in[22];
    float* out = (float*)d_out;

    k_cvt_h<<<(Nn * IND) / 256, 256>>>(h);
    k_cvt_w<<<(IND * NOUT) / 256, 256>>>(W1);
    k_p1mma<<<dim3(NOUT / 128, Nn / 128), 256>>>(b1);
    k_p2<<<Nn, 64>>>(h, Wp2, bp2);

    k_zero<<<8, 256>>>();
    k_hist<<<Ee / 256, 256>>>(src);
    k_scan<<<1, 256>>>();
    k_scatter<<<Ee / 256, 256>>>(src);

    k_local<<<Ee / 8, 128>>>(local_, ein, src, dst, ln_w, ln_b, conv_w, conv_b,
                             W2, b2, bnL_g, bnL_b, out);
    k_global<<<Nn, 256>>>(dst, W3, b3, bng_g, bng_b, bnG_g, bnG_b, out);
}

// round 4
// speedup vs baseline: 1.4624x; 1.4624x over previous
#include <cuda_runtime.h>
#include <cstdint>

#define Nn   2048
#define IND  128
#define HIDD 64
#define Ee   32768
#define EPSf 1e-5f
#define NOUT 4096   /* HIDD*HIDD */

// -------- scratch (device globals; no allocation allowed) --------
__device__ __align__(256) float g_p1[Nn * NOUT];   // relu(h@W1+b1)
__device__ __align__(256) float g_p2[Nn * HIDD];   // relu(h@Wp2+bp2)
__device__ int g_cnt[Nn];
__device__ int g_off[Nn + 1];
__device__ int g_cur[Nn];
__device__ int g_eidx[Ee];

// ================= edge bucketing by src =================
__global__ void k_zero() {
    int i = blockIdx.x * blockDim.x + threadIdx.x;
    if (i < Nn) g_cnt[i] = 0;
}
__global__ void k_hist(const int* __restrict__ src) {
    int e = blockIdx.x * blockDim.x + threadIdx.x;
    if (e < Ee) atomicAdd(&g_cnt[src[e]], 1);
}
__global__ void k_scan() {
    __shared__ int part[256];
    int t = threadIdx.x;
    int base = t * 8;
    int loc[8];
    int s = 0;
#pragma unroll
    for (int i = 0; i < 8; i++) { loc[i] = g_cnt[base + i]; s += loc[i]; }
    part[t] = s;
    __syncthreads();
    if (t == 0) {
        int run = 0;
        for (int i = 0; i < 256; i++) { int v = part[i]; part[i] = run; run += v; }
    }
    __syncthreads();
    int run = part[t];
#pragma unroll
    for (int i = 0; i < 8; i++) {
        g_off[base + i] = run;
        g_cur[base + i] = run;
        run += loc[i];
    }
    if (t == 255) g_off[Nn] = run;
}
__global__ void k_scatter(const int* __restrict__ src) {
    int e = blockIdx.x * blockDim.x + threadIdx.x;
    if (e < Ee) {
        int s = src[e];
        int p = atomicAdd(&g_cur[s], 1);
        g_eidx[p] = e;
    }
}

// ================= p1 = relu(h @ W1 + b1) via 3xTF32 mma.sync =================
#define ASTR 68    /* A smem k-stride (floats): frag bank = 4g+t, conflict-free */
#define BSTR 136   /* B smem n-stride (floats): frag bank = 8t+g, conflict-free */
#define KC   64
#define P1_SMEM ((128 * ASTR + KC * BSTR) * 4)

__device__ __forceinline__ uint32_t f2tf(float x) {
    uint32_t r;
    asm("cvt.rna.tf32.f32 %0, %1;" : "=r"(r) : "f"(x));
    return r;
}

__device__ __forceinline__ void mma_tf32(float* d, const uint32_t* a, const uint32_t* b) {
    asm volatile(
        "mma.sync.aligned.m16n8k8.row.col.f32.tf32.tf32.f32 "
        "{%0,%1,%2,%3}, {%4,%5,%6,%7}, {%8,%9}, {%0,%1,%2,%3};"
        : "+f"(d[0]), "+f"(d[1]), "+f"(d[2]), "+f"(d[3])
        : "r"(a[0]), "r"(a[1]), "r"(a[2]), "r"(a[3]), "r"(b[0]), "r"(b[1]));
}

__global__ __launch_bounds__(256) void k_p1tf(const float* __restrict__ h,
                                              const float* __restrict__ W1,
                                              const float* __restrict__ b1) {
    extern __shared__ float sm[];
    float* As = sm;                    // [128][ASTR]  A[m][k]
    float* Bs = sm + 128 * ASTR;       // [KC][BSTR]   B[k][n]

    int tid = threadIdx.x;
    int wid = tid >> 5, lane = tid & 31;
    int g = lane >> 2, t = lane & 3;
    int warp_m = (wid >> 2) * 64;      // 0 or 64
    int warp_n = (wid & 3) * 32;       // 0..96
    int row0 = blockIdx.y * 128;
    int col0 = blockIdx.x * 128;

    float acc[4][4][4];
#pragma unroll
    for (int mi = 0; mi < 4; mi++)
#pragma unroll
        for (int ni = 0; ni < 4; ni++)
#pragma unroll
            for (int r = 0; r < 4; r++) acc[mi][ni][r] = 0.f;

    for (int kc = 0; kc < IND; kc += KC) {
        // A chunk: h[row0+m][kc..kc+63]  (2048 float4, 8/thread)
#pragma unroll
        for (int it = 0; it < 8; it++) {
            int chunk = tid + it * 256;
            int m = chunk >> 4;
            int k4 = (chunk & 15) * 4;
            float4 v = *(const float4*)&h[(row0 + m) * IND + kc + k4];
            *(float4*)&As[m * ASTR + k4] = v;
        }
        // B chunk: W1[kc+k][col0..col0+127] kept [k][n]  (2048 float4)
#pragma unroll
        for (int it = 0; it < 8; it++) {
            int chunk = tid + it * 256;
            int k = chunk >> 5;
            int n4 = (chunk & 31) * 4;
            float4 v = *(const float4*)&W1[(kc + k) * NOUT + col0 + n4];
            *(float4*)&Bs[k * BSTR + n4] = v;
        }
        __syncthreads();

#pragma unroll
        for (int ks = 0; ks < KC; ks += 8) {
            uint32_t ahi[4][4], alo[4][4], bhi[4][2], blo[4][2];
#pragma unroll
            for (int mi = 0; mi < 4; mi++) {
                int r = warp_m + mi * 16 + g;
                float a0 = As[r * ASTR + ks + t];
                float a1 = As[(r + 8) * ASTR + ks + t];
                float a2 = As[r * ASTR + ks + t + 4];
                float a3 = As[(r + 8) * ASTR + ks + t + 4];
                ahi[mi][0] = f2tf(a0); alo[mi][0] = f2tf(a0 - __uint_as_float(ahi[mi][0]));
                ahi[mi][1] = f2tf(a1); alo[mi][1] = f2tf(a1 - __uint_as_float(ahi[mi][1]));
                ahi[mi][2] = f2tf(a2); alo[mi][2] = f2tf(a2 - __uint_as_float(ahi[mi][2]));
                ahi[mi][3] = f2tf(a3); alo[mi][3] = f2tf(a3 - __uint_as_float(ahi[mi][3]));
            }
#pragma unroll
            for (int ni = 0; ni < 4; ni++) {
                int n = warp_n + ni * 8 + g;
                float b0 = Bs[(ks + t) * BSTR + n];
                float b1v = Bs[(ks + t + 4) * BSTR + n];
                bhi[ni][0] = f2tf(b0);  blo[ni][0] = f2tf(b0 - __uint_as_float(bhi[ni][0]));
                bhi[ni][1] = f2tf(b1v); blo[ni][1] = f2tf(b1v - __uint_as_float(bhi[ni][1]));
            }
#pragma unroll
            for (int mi = 0; mi < 4; mi++)
#pragma unroll
                for (int ni = 0; ni < 4; ni++) {
                    mma_tf32(acc[mi][ni], ahi[mi], bhi[ni]);
                    mma_tf32(acc[mi][ni], ahi[mi], blo[ni]);
                    mma_tf32(acc[mi][ni], alo[mi], bhi[ni]);
                }
        }
        __syncthreads();
    }

    // epilogue: bias + relu -> g_p1
#pragma unroll
    for (int mi = 0; mi < 4; mi++) {
        int r = row0 + warp_m + mi * 16 + g;
#pragma unroll
        for (int ni = 0; ni < 4; ni++) {
            int c = col0 + warp_n + ni * 8 + t * 2;
            float2 bb = *(const float2*)&b1[c];
            float2 o0, o1;
            o0.x = fmaxf(acc[mi][ni][0] + bb.x, 0.f);
            o0.y = fmaxf(acc[mi][ni][1] + bb.y, 0.f);
            o1.x = fmaxf(acc[mi][ni][2] + bb.x, 0.f);
            o1.y = fmaxf(acc[mi][ni][3] + bb.y, 0.f);
            *(float2*)&g_p1[(size_t)r * NOUT + c] = o0;
            *(float2*)&g_p1[(size_t)(r + 8) * NOUT + c] = o1;
        }
    }
}

// ================= p2 = relu(h @ Wp2 + bp2), 4 rows/block =================
__global__ __launch_bounds__(256) void k_p2(const float* __restrict__ h,
                                            const float* __restrict__ Wp2,
                                            const float* __restrict__ bp2) {
    __shared__ float hs[4][IND];
    int t = threadIdx.x;
    int row0 = blockIdx.x * 4;
#pragma unroll
    for (int i = t; i < 4 * IND; i += 256)
        hs[i >> 7][i & 127] = h[(row0 + (i >> 7)) * IND + (i & 127)];
    __syncthreads();
    int r = t >> 6, j = t & 63;
    float acc = bp2[j];
#pragma unroll 8
    for (int k = 0; k < IND; k++) acc += hs[r][k] * Wp2[k * HIDD + j];
    g_p2[(row0 + r) * HIDD + j] = fmaxf(acc, 0.f);
}

// ================= local branch =================
__global__ __launch_bounds__(128) void k_local(const float* __restrict__ local,
                                               const float* __restrict__ ein,
                                               const int* __restrict__ src,
                                               const int* __restrict__ dst,
                                               const float* __restrict__ ln_w,
                                               const float* __restrict__ ln_b,
                                               const float* __restrict__ conv_w,
                                               const float* __restrict__ conv_b,
                                               const float* __restrict__ W2,
                                               const float* __restrict__ b2,
                                               const float* __restrict__ bnL_g,
                                               const float* __restrict__ bnL_b,
                                               float* __restrict__ out) {
    __shared__ float W2s[IND * HIDD];
    __shared__ float Tsm[8][IND];
    __shared__ float sa[IND + 2], sb[IND + 2];
    __shared__ float4 red[4];

    int t = threadIdx.x;
    for (int i = t; i < IND * HIDD; i += 128) W2s[i] = W2[i];
    float lw = ln_w[t], lb = ln_b[t];
    float cw0 = conv_w[0], cw1 = conv_w[1], cw2 = conv_w[2];
    float cw3 = conv_w[3], cw4 = conv_w[4], cw5 = conv_w[5];
    float cb = conv_b[0];
    int e0 = blockIdx.x * 8;
    int lane = t & 31, warp = t >> 5;
    if (t == 0) { sa[0] = 0.f; sa[IND + 1] = 0.f; sb[0] = 0.f; sb[IND + 1] = 0.f; }

    for (int eo = 0; eo < 8; eo++) {
        int e = e0 + eo;
        int s = src[e], dd = dst[e];
        float a = local[s * IND + t];
        float b = local[dd * IND + t];
        float4 v = make_float4(a, a * a, b, b * b);
#pragma unroll
        for (int o = 16; o; o >>= 1) {
            v.x += __shfl_down_sync(0xffffffffu, v.x, o);
            v.y += __shfl_down_sync(0xffffffffu, v.y, o);
            v.z += __shfl_down_sync(0xffffffffu, v.z, o);
            v.w += __shfl_down_sync(0xffffffffu, v.w, o);
        }
        if (lane == 0) red[warp] = v;
        __syncthreads();
        float4 tot = red[0];
        tot.x += red[1].x + red[2].x + red[3].x;
        tot.y += red[1].y + red[2].y + red[3].y;
        tot.z += red[1].z + red[2].z + red[3].z;
        tot.w += red[1].w + red[2].w + red[3].w;
        float mua = tot.x * (1.f / IND), vara = tot.y * (1.f / IND) - mua * mua;
        float mub = tot.z * (1.f / IND), varb = tot.w * (1.f / IND) - mub * mub;
        float an = (a - mua) * rsqrtf(vara + EPSf) * lw + lb;
        float bn_ = (b - mub) * rsqrtf(varb + EPSf) * lw + lb;
        sa[t + 1] = an;
        sb[t + 1] = bn_;
        __syncthreads();
        float c = cw0 * sa[t] + cw1 * sa[t + 1] + cw2 * sa[t + 2]
                + cw3 * sb[t] + cw4 * sb[t + 1] + cw5 * sb[t + 2] + cb;
        Tsm[eo][t] = fmaxf(c, 0.f);
        __syncthreads();
    }

    int j = t & 63, half = t >> 6;
    float c0 = 0.f, c1 = 0.f, c2 = 0.f, c3 = 0.f;
#pragma unroll 4
    for (int i = 0; i < IND; i++) {
        float w = W2s[i * HIDD + j];
        c0 += Tsm[half + 0][i] * w;
        c1 += Tsm[half + 2][i] * w;
        c2 += Tsm[half + 4][i] * w;
        c3 += Tsm[half + 6][i] * w;
    }
    float rs = rsqrtf(1.f + EPSf);
    float sL = bnL_g[j] * rs, bL = bnL_b[j];
    float bb = b2[j];
    float r0 = fmaxf((c0 + bb) * sL + bL, 0.f);
    float r1 = fmaxf((c1 + bb) * sL + bL, 0.f);
    float r2 = fmaxf((c2 + bb) * sL + bL, 0.f);
    float r3 = fmaxf((c3 + bb) * sL + bL, 0.f);
    out[(e0 + half + 0) * HIDD + j] = r0 + ein[(e0 + half + 0) * HIDD + j];
    out[(e0 + half + 2) * HIDD + j] = r1 + ein[(e0 + half + 2) * HIDD + j];
    out[(e0 + half + 4) * HIDD + j] = r2 + ein[(e0 + half + 4) * HIDD + j];
    out[(e0 + half + 6) * HIDD + j] = r3 + ein[(e0 + half + 6) * HIDD + j];
}

// ================= global branch: one block per src node =================
__global__ __launch_bounds__(256) void k_global(const int* __restrict__ dst,
                                                const float* __restrict__ W3,
                                                const float* __restrict__ b3,
                                                const float* __restrict__ bng_g,
                                                const float* __restrict__ bng_b,
                                                const float* __restrict__ bnG_g,
                                                const float* __restrict__ bnG_b,
                                                float* __restrict__ out) {
    __shared__ float p1s[HIDD][HIDD + 1];   // [k][d], padded
    __shared__ float W3s[HIDD * HIDD];
    __shared__ float p2s[4][HIDD];
    __shared__ float zs[4][HIDD];

    int node = blockIdx.x;
    int t = threadIdx.x;
    int beg = g_off[node], end = g_off[node + 1];
    if (beg == end) return;

    const float* p1row = &g_p1[node * NOUT];
    for (int jdx = t; jdx < HIDD * HIDD; jdx += 256) {
        int d = jdx >> 6, k = jdx & 63;
        p1s[k][d] = p1row[jdx];
    }
    for (int jdx = t; jdx < HIDD * HIDD; jdx += 256) W3s[jdx] = W3[jdx];

    int d = t & 63, g = t >> 6;
    float rs = rsqrtf(1.f + EPSf);
    float s1 = bng_g[d] * rs, o1 = bng_b[d];
    float s2 = bnG_g[d] * rs, o2 = bnG_b[d];
    float b3v = b3[d];
    __syncthreads();

    for (int base = beg; base < end; base += 4) {
        int ei = base + g;
        bool valid = ei < end;
        int e = 0;
        if (valid) {
            e = g_eidx[ei];
            int dn = dst[e];
            p2s[g][d] = g_p2[dn * HIDD + d];
        }
        __syncthreads();
        if (valid) {
            float y = 0.f;
#pragma unroll 8
            for (int k = 0; k < HIDD; k++) y += p1s[k][d] * p2s[g][k];
            zs[g][d] = y * s1 + o1;
        }
        __syncthreads();
        if (valid) {
            float o = b3v;
#pragma unroll 8
            for (int k = 0; k < HIDD; k++) o += zs[g][k] * W3s[k * HIDD + d];
            float v = fmaxf(o * s2 + o2, 0.f);
            out[e * HIDD + d] += v;
        }
        __syncthreads();
    }
}

// ================= launch =================
extern "C" void kernel_launch(void* const* d_in, const int* in_sizes, int n_in,
                              void* d_out, int out_size) {
    const float* h      = (const float*)d_in[0];
    const float* local_ = (const float*)d_in[1];
    const float* ein    = (const float*)d_in[2];
    const int*   src    = (const int*)d_in[3];
    const int*   dst    = (const int*)d_in[4];
    const float* ln_w   = (const float*)d_in[5];
    const float* ln_b   = (const float*)d_in[6];
    const float* conv_w = (const float*)d_in[7];
    const float* conv_b = (const float*)d_in[8];
    const float* W1     = (const float*)d_in[9];
    const float* b1     = (const float*)d_in[10];
    const float* Wp2    = (const float*)d_in[11];
    const float* bp2    = (const float*)d_in[12];
    const float* W2     = (const float*)d_in[13];
    const float* b2     = (const float*)d_in[14];
    const float* W3     = (const float*)d_in[15];
    const float* b3     = (const float*)d_in[16];
    const float* bng_g  = (const float*)d_in[17];
    const float* bng_b  = (const float*)d_in[18];
    const float* bnG_g  = (const float*)d_in[19];
    const float* bnG_b  = (const float*)d_in[20];
    const float* bnL_g  = (const float*)d_in[21];
    const float* bnL_b  = (const float*)d_in[22];
    float* out = (float*)d_out;

    static int smem_set = 0;
    if (!smem_set) {
        cudaFuncSetAttribute(k_p1tf, cudaFuncAttributeMaxDynamicSharedMemorySize, P1_SMEM);
        smem_set = 1;
    }

    k_p1tf<<<dim3(NOUT / 128, Nn / 128), 256, P1_SMEM>>>(h, W1, b1);
    k_p2<<<Nn / 4, 256>>>(h, Wp2, bp2);

    k_zero<<<8, 256>>>();
    k_hist<<<Ee / 256, 256>>>(src);
    k_scan<<<1, 256>>>();
    k_scatter<<<Ee / 256, 256>>>(src);

    k_local<<<Ee / 8, 128>>>(local_, ein, src, dst, ln_w, ln_b, conv_w, conv_b,
                             W2, b2, bnL_g, bnL_b, out);
    k_global<<<Nn, 256>>>(dst, W3, b3, bng_g, bng_b, bnG_g, bnG_b, out);
}